// round 1
// baseline (speedup 1.0000x reference)
#include <cuda_runtime.h>
#include <cuda_bf16.h>

#define N_NODES 50000
#define N_EDGES 800000
#define HEADS 8
#define ADIM 8
#define HD 64            // HEADS*ADIM
#define CLAMP_V 5.0f

// ---------------- scratch (device globals: allocation-free rule) ----------------
__device__ __align__(16) float g_Q[N_NODES * HD];
__device__ __align__(16) float g_K[N_NODES * HD];
__device__ __align__(16) float g_V[N_NODES * HD];
__device__ __align__(16) float g_w[N_EDGES * HEADS];   // exp(clamped score)
__device__ int g_count[N_NODES];
__device__ int g_off[N_NODES + 1];
__device__ int g_cursor[N_NODES];
__device__ int g_order[N_EDGES];

// ---------------- f32x2 packed FMA helpers (FFMA2) ----------------
__device__ __forceinline__ unsigned long long pk2(float lo, float hi) {
    unsigned long long r;
    asm("mov.b64 %0, {%1, %2};" : "=l"(r) : "f"(lo), "f"(hi));
    return r;
}
__device__ __forceinline__ void fma2(unsigned long long& d, unsigned long long a, unsigned long long b) {
    asm("fma.rn.f32x2 %0, %1, %2, %0;" : "+l"(d) : "l"(a), "l"(b));
}
__device__ __forceinline__ float2 upk2(unsigned long long v) {
    float lo, hi;
    asm("mov.b64 {%0, %1}, %2;" : "=f"(lo), "=f"(hi) : "l"(v));
    return make_float2(lo, hi);
}

// ---------------- kernel 1: QKV = x @ qkv_weight.T + bias ----------------
// grid (ceil(N/64), 3), block 256. part selects Q/K/V (64 output cols each).
__global__ __launch_bounds__(256) void qkv_kernel(
    const float* __restrict__ x, const float* __restrict__ W, const float* __restrict__ bias)
{
    __shared__ float xS[64 * 68];
    __shared__ float wS[64 * 68];   // wS[k*68 + c] = W[(part*64+c)*64 + k]
    const int part = blockIdx.y;
    const int row0 = blockIdx.x * 64;
    const int tid = threadIdx.x;

    #pragma unroll
    for (int p = 0; p < 4; p++) {
        int idx = tid + p * 256;         // float4 index into 64x64 tile
        int r = idx >> 4, c4 = idx & 15;
        float4 v = make_float4(0.f, 0.f, 0.f, 0.f);
        int gr = row0 + r;
        if (gr < N_NODES) v = ((const float4*)x)[gr * 16 + c4];
        *(float4*)&xS[r * 68 + c4 * 4] = v;
    }
    #pragma unroll
    for (int p = 0; p < 4; p++) {
        int idx = tid + p * 256;
        int c = idx >> 4, f = idx & 15;
        float4 v = ((const float4*)W)[(part * 64 + c) * 16 + f];
        wS[(f * 4 + 0) * 68 + c] = v.x;
        wS[(f * 4 + 1) * 68 + c] = v.y;
        wS[(f * 4 + 2) * 68 + c] = v.z;
        wS[(f * 4 + 3) * 68 + c] = v.w;
    }
    __syncthreads();

    const int tx = tid & 15, ty = tid >> 4;   // 4 cols x 4 rows per thread
    unsigned long long acc[4][2];
    #pragma unroll
    for (int i = 0; i < 4; i++) { acc[i][0] = 0ull; acc[i][1] = 0ull; }

    #pragma unroll 4
    for (int k = 0; k < 64; k++) {
        float4 b = *(float4*)&wS[k * 68 + tx * 4];
        unsigned long long b0 = pk2(b.x, b.y), b1 = pk2(b.z, b.w);
        #pragma unroll
        for (int i = 0; i < 4; i++) {
            float a = xS[(ty * 4 + i) * 68 + k];
            unsigned long long a2 = pk2(a, a);
            fma2(acc[i][0], a2, b0);
            fma2(acc[i][1], a2, b1);
        }
    }

    float* outBase = (part == 0) ? g_Q : (part == 1 ? g_K : g_V);
    float4 bv = ((const float4*)bias)[part * 16 + tx];
    #pragma unroll
    for (int i = 0; i < 4; i++) {
        int gr = row0 + ty * 4 + i;
        if (gr < N_NODES) {
            float2 p0 = upk2(acc[i][0]), p1 = upk2(acc[i][1]);
            float4 o = make_float4(p0.x + bv.x, p0.y + bv.y, p1.x + bv.z, p1.y + bv.w);
            *(float4*)&outBase[gr * 64 + tx * 4] = o;
        }
    }
}

// ---------------- CSR construction ----------------
__global__ void zero_kernel() {
    int i = blockIdx.x * blockDim.x + threadIdx.x;
    if (i < N_NODES) g_count[i] = 0;
}
__global__ void count_kernel(const int* __restrict__ eidx) {
    int e = blockIdx.x * blockDim.x + threadIdx.x;
    if (e < N_EDGES) atomicAdd(&g_count[eidx[e]], 1);
}
__global__ void scan_kernel() {
    __shared__ int part[1024];
    const int C = (N_NODES + 1023) / 1024;
    int t = threadIdx.x;
    int base = t * C;
    int s = 0;
    for (int i = 0; i < C; i++) {
        int idx = base + i;
        if (idx < N_NODES) s += g_count[idx];
    }
    part[t] = s;
    __syncthreads();
    for (int off = 1; off < 1024; off <<= 1) {
        int v = (t >= off) ? part[t - off] : 0;
        __syncthreads();
        part[t] += v;
        __syncthreads();
    }
    int run = (t > 0) ? part[t - 1] : 0;
    for (int i = 0; i < C; i++) {
        int idx = base + i;
        if (idx < N_NODES) {
            g_off[idx] = run;
            g_cursor[idx] = run;
            run += g_count[idx];
        }
    }
    if (t == 1023) g_off[N_NODES] = run;
}
__global__ void scatter_kernel(const int* __restrict__ eidx) {
    int e = blockIdx.x * blockDim.x + threadIdx.x;
    if (e < N_EDGES) {
        int dst = eidx[e];
        int pos = atomicAdd(&g_cursor[dst], 1);
        g_order[pos] = e;
    }
}

// ---------------- kernel 2: fused edge GEMM + conn + score ----------------
// block = 128 edges, 256 threads. thread = 4 edges x 1 head x {Ew(8), Eb(8)}.
__global__ __launch_bounds__(256, 2) void edge_kernel(
    const float* __restrict__ cf, const float* __restrict__ EW,
    const float* __restrict__ Ebias, const int* __restrict__ eidx,
    const float* __restrict__ Aw, float* __restrict__ conn_out)
{
    extern __shared__ float sm[];
    float* cfS = sm;                      // 128*68
    float* wS = cfS + 128 * 68;           // 64*132 : wS[k*132 + n] = EW[n*64+k]
    float* awS = wS + 64 * 132;           // 64
    float* ebS = awS + 64;                // 128
    int* sDst = (int*)(ebS + 128);        // 128
    int* sSrc = sDst + 128;               // 128

    const int tid = threadIdx.x;
    const int e0 = blockIdx.x * 128;

    #pragma unroll
    for (int p = 0; p < 8; p++) {
        int idx = tid + p * 256;          // float4 index over 128x64 cf tile
        int r = idx >> 4, c4 = idx & 15;
        float4 v = ((const float4*)cf)[(e0 + r) * 16 + c4];
        *(float4*)&cfS[r * 68 + c4 * 4] = v;
    }
    #pragma unroll
    for (int p = 0; p < 8; p++) {
        int idx = tid + p * 256;          // float4 index over 128x64 EW
        int n = idx >> 4, f = idx & 15;
        float4 v = ((const float4*)EW)[n * 16 + f];
        wS[(f * 4 + 0) * 132 + n] = v.x;
        wS[(f * 4 + 1) * 132 + n] = v.y;
        wS[(f * 4 + 2) * 132 + n] = v.z;
        wS[(f * 4 + 3) * 132 + n] = v.w;
    }
    if (tid < 64) awS[tid] = Aw[tid];
    if (tid >= 64 && tid < 192) ebS[tid - 64] = Ebias[tid - 64];
    if (tid < 128) {
        sDst[tid] = eidx[e0 + tid];
        sSrc[tid] = eidx[N_EDGES + e0 + tid];
    }
    __syncthreads();

    const int tx = tid & 7;               // head
    const int tg = tid >> 3;              // edge group (4 edges)

    unsigned long long acc[4][8];
    #pragma unroll
    for (int i = 0; i < 4; i++)
        #pragma unroll
        for (int p = 0; p < 8; p++) acc[i][p] = 0ull;

    #pragma unroll 2
    for (int k = 0; k < 64; k++) {
        const float* wr = &wS[k * 132];
        float4 w0 = *(const float4*)&wr[tx * 8];
        float4 w1 = *(const float4*)&wr[tx * 8 + 4];
        float4 w2 = *(const float4*)&wr[64 + tx * 8];
        float4 w3 = *(const float4*)&wr[64 + tx * 8 + 4];
        unsigned long long b[8];
        b[0] = pk2(w0.x, w0.y); b[1] = pk2(w0.z, w0.w);
        b[2] = pk2(w1.x, w1.y); b[3] = pk2(w1.z, w1.w);
        b[4] = pk2(w2.x, w2.y); b[5] = pk2(w2.z, w2.w);
        b[6] = pk2(w3.x, w3.y); b[7] = pk2(w3.z, w3.w);
        #pragma unroll
        for (int i = 0; i < 4; i++) {
            float a = cfS[(tg * 4 + i) * 68 + k];
            unsigned long long a2 = pk2(a, a);
            #pragma unroll
            for (int p = 0; p < 8; p++) fma2(acc[i][p], a2, b[p]);
        }
    }

    // epilogue per edge: conn1 -> signed sqrt -> +Eb -> relu -> write; score -> w
    #pragma unroll
    for (int i = 0; i < 4; i++) {
        int el = tg * 4 + i;
        int e = e0 + el;
        int d = sDst[el], s = sSrc[el];
        float4 q0 = ((const float4*)g_Q)[d * 16 + tx * 2];
        float4 q1 = ((const float4*)g_Q)[d * 16 + tx * 2 + 1];
        float4 k0 = ((const float4*)g_K)[s * 16 + tx * 2];
        float4 k1 = ((const float4*)g_K)[s * 16 + tx * 2 + 1];
        float qk[8] = {q0.x + k0.x, q0.y + k0.y, q0.z + k0.z, q0.w + k0.w,
                       q1.x + k1.x, q1.y + k1.y, q1.z + k1.z, q1.w + k1.w};
        float ew[8], eb[8];
        #pragma unroll
        for (int p = 0; p < 4; p++) {
            float2 u = upk2(acc[i][p]);
            ew[2 * p] = u.x; ew[2 * p + 1] = u.y;
            float2 v = upk2(acc[i][4 + p]);
            eb[2 * p] = v.x; eb[2 * p + 1] = v.y;
        }
        float conn[8];
        #pragma unroll
        for (int j = 0; j < 8; j++) {
            float c1 = qk[j] * (ew[j] + ebS[tx * 8 + j]);
            float c2 = copysignf(sqrtf(fabsf(c1)), c1);
            conn[j] = fmaxf(c2 + (eb[j] + ebS[64 + tx * 8 + j]), 0.f);
        }
        float* co = &conn_out[(long long)e * 64 + tx * 8];
        *(float4*)co = make_float4(conn[0], conn[1], conn[2], conn[3]);
        *(float4*)(co + 4) = make_float4(conn[4], conn[5], conn[6], conn[7]);
        float sc = 0.f;
        #pragma unroll
        for (int j = 0; j < 8; j++) sc = fmaf(conn[j], awS[j * 8 + tx], sc);
        sc = fminf(fmaxf(sc, -CLAMP_V), CLAMP_V);
        g_w[e * 8 + tx] = expf(sc);
    }
}

// ---------------- kernel 3: per-node aggregation (warp per node) ----------------
__global__ __launch_bounds__(256) void node_kernel(
    const float* __restrict__ conn_out, const int* __restrict__ eidx,
    const float* __restrict__ Bw, float* __restrict__ No)
{
    __shared__ float bwS[512];
    int tid = threadIdx.x;
    bwS[tid] = Bw[tid];
    bwS[tid + 256] = Bw[tid + 256];
    __syncthreads();

    const int warp = tid >> 5, lane = tid & 31;
    const int n = blockIdx.x * 8 + warp;
    const int j0 = g_off[n], j1 = g_off[n + 1];
    const int h0 = lane >> 3, h1 = h0 + 4, c = lane & 7, base = lane & 24;
    const int* srcArr = eidx + N_EDGES;

    float s0 = 0.f, s1 = 0.f, agg0 = 0.f, agg1 = 0.f, rv0 = 0.f, rv1 = 0.f;
    for (int j = j0; j < j1; j++) {
        int e = g_order[j];
        int src = srcArr[e];
        float w0 = g_w[e * 8 + h0];
        float w1 = g_w[e * 8 + h1];
        float c0 = conn_out[(long long)e * 64 + lane];
        float c1 = conn_out[(long long)e * 64 + 32 + lane];
        float v0 = g_V[src * 64 + lane];
        float v1 = g_V[src * 64 + 32 + lane];
        s0 += w0; s1 += w1;
        agg0 = fmaf(w0, v0, agg0); rv0 = fmaf(w0, c0, rv0);
        agg1 = fmaf(w1, v1, agg1); rv1 = fmaf(w1, c1, rv1);
    }
    float inv0 = (s0 > 0.f) ? 1.f / s0 : 0.f;
    float inv1 = (s1 > 0.f) ? 1.f / s1 : 0.f;
    float rn0 = rv0 * inv0, rn1 = rv1 * inv1;
    float o0 = 0.f, o1 = 0.f;
    #pragma unroll
    for (int d = 0; d < 8; d++) {
        float r0 = __shfl_sync(0xffffffffu, rn0, base + d);
        float r1 = __shfl_sync(0xffffffffu, rn1, base + d);
        o0 = fmaf(r0, bwS[d * 64 + h0 * 8 + c], o0);
        o1 = fmaf(r1, bwS[d * 64 + h1 * 8 + c], o1);
    }
    No[n * 64 + lane] = fmaf(agg0, inv0, o0);
    No[n * 64 + 32 + lane] = fmaf(agg1, inv1, o1);
}

// ---------------- launch ----------------
extern "C" void kernel_launch(void* const* d_in, const int* in_sizes, int n_in,
                              void* d_out, int out_size)
{
    const float* x       = (const float*)d_in[0];
    const float* cf      = (const float*)d_in[1];
    const int*   eidx    = (const int*)d_in[2];
    const float* qkvW    = (const float*)d_in[3];
    const float* qkvB    = (const float*)d_in[4];
    const float* EW      = (const float*)d_in[5];
    const float* EB      = (const float*)d_in[6];
    const float* Aw      = (const float*)d_in[7];
    const float* Bw      = (const float*)d_in[8];

    float* No = (float*)d_out;
    float* conn_out = No + (size_t)N_NODES * 64;

    const int edge_smem = (128 * 68 + 64 * 132 + 64 + 128) * 4 + 256 * 4;
    cudaFuncSetAttribute(edge_kernel, cudaFuncAttributeMaxDynamicSharedMemorySize, edge_smem);

    zero_kernel<<<(N_NODES + 255) / 256, 256>>>();
    qkv_kernel<<<dim3((N_NODES + 63) / 64, 3), 256>>>(x, qkvW, qkvB);
    count_kernel<<<(N_EDGES + 255) / 256, 256>>>(eidx);
    scan_kernel<<<1, 1024>>>();
    scatter_kernel<<<(N_EDGES + 255) / 256, 256>>>(eidx);
    edge_kernel<<<N_EDGES / 128, 256, edge_smem>>>(cf, EW, EB, eidx, Aw, conn_out);
    node_kernel<<<N_NODES / 8, 256>>>(conn_out, eidx, Bw, No);
}

// round 2
// speedup vs baseline: 1.0792x; 1.0792x over previous
#include <cuda_runtime.h>
#include <cuda_bf16.h>

#define N_NODES 50000
#define N_EDGES 800000
#define HEADS 8
#define ADIM 8
#define HD 64            // HEADS*ADIM
#define CLAMP_V 5.0f
#define SCAN_BLK 196     // ceil(50000/256)

// ---------------- scratch (device globals: allocation-free rule) ----------------
__device__ __align__(16) float g_Q[N_NODES * HD];
__device__ __align__(16) float g_K[N_NODES * HD];
__device__ __align__(16) float g_V[N_NODES * HD];
__device__ __align__(16) float g_w[N_EDGES * HEADS];   // exp(clamped score)
__device__ int g_count[N_NODES];
__device__ int g_off[N_NODES + 1];
__device__ int g_cursor[N_NODES];
__device__ int g_order[N_EDGES];
__device__ int g_bsum[SCAN_BLK];
__device__ int g_boff[SCAN_BLK];

// ---------------- f32x2 packed FMA helpers (FFMA2) ----------------
__device__ __forceinline__ unsigned long long pk2(float lo, float hi) {
    unsigned long long r;
    asm("mov.b64 %0, {%1, %2};" : "=l"(r) : "f"(lo), "f"(hi));
    return r;
}
__device__ __forceinline__ void fma2(unsigned long long& d, unsigned long long a, unsigned long long b) {
    asm("fma.rn.f32x2 %0, %1, %2, %0;" : "+l"(d) : "l"(a), "l"(b));
}
__device__ __forceinline__ float2 upk2(unsigned long long v) {
    float lo, hi;
    asm("mov.b64 {%0, %1}, %2;" : "=f"(lo), "=f"(hi) : "l"(v));
    return make_float2(lo, hi);
}

// ---------------- kernel 1: QKV = x @ qkv_weight.T + bias ----------------
__global__ __launch_bounds__(256) void qkv_kernel(
    const float* __restrict__ x, const float* __restrict__ W, const float* __restrict__ bias)
{
    __shared__ float xS[64 * 68];
    __shared__ float wS[64 * 68];   // wS[k*68 + c] = W[(part*64+c)*64 + k]
    const int part = blockIdx.y;
    const int row0 = blockIdx.x * 64;
    const int tid = threadIdx.x;

    #pragma unroll
    for (int p = 0; p < 4; p++) {
        int idx = tid + p * 256;         // float4 index into 64x64 tile
        int r = idx >> 4, c4 = idx & 15;
        float4 v = make_float4(0.f, 0.f, 0.f, 0.f);
        int gr = row0 + r;
        if (gr < N_NODES) v = ((const float4*)x)[gr * 16 + c4];
        *(float4*)&xS[r * 68 + c4 * 4] = v;
    }
    #pragma unroll
    for (int p = 0; p < 4; p++) {
        int idx = tid + p * 256;
        int c = idx >> 4, f = idx & 15;
        float4 v = ((const float4*)W)[(part * 64 + c) * 16 + f];
        wS[(f * 4 + 0) * 68 + c] = v.x;
        wS[(f * 4 + 1) * 68 + c] = v.y;
        wS[(f * 4 + 2) * 68 + c] = v.z;
        wS[(f * 4 + 3) * 68 + c] = v.w;
    }
    __syncthreads();

    const int tx = tid & 15, ty = tid >> 4;   // 4 cols x 4 rows per thread
    unsigned long long acc[4][2];
    #pragma unroll
    for (int i = 0; i < 4; i++) { acc[i][0] = 0ull; acc[i][1] = 0ull; }

    #pragma unroll 4
    for (int k = 0; k < 64; k++) {
        float4 b = *(float4*)&wS[k * 68 + tx * 4];
        unsigned long long b0 = pk2(b.x, b.y), b1 = pk2(b.z, b.w);
        #pragma unroll
        for (int i = 0; i < 4; i++) {
            float a = xS[(ty * 4 + i) * 68 + k];
            unsigned long long a2 = pk2(a, a);
            fma2(acc[i][0], a2, b0);
            fma2(acc[i][1], a2, b1);
        }
    }

    float* outBase = (part == 0) ? g_Q : (part == 1 ? g_K : g_V);
    float4 bv = ((const float4*)bias)[part * 16 + tx];
    #pragma unroll
    for (int i = 0; i < 4; i++) {
        int gr = row0 + ty * 4 + i;
        if (gr < N_NODES) {
            float2 p0 = upk2(acc[i][0]), p1 = upk2(acc[i][1]);
            float4 o = make_float4(p0.x + bv.x, p0.y + bv.y, p1.x + bv.z, p1.y + bv.w);
            *(float4*)&outBase[gr * 64 + tx * 4] = o;
        }
    }
}

// ---------------- CSR construction ----------------
__global__ void zero_kernel() {
    int i = blockIdx.x * blockDim.x + threadIdx.x;
    if (i < N_NODES) g_count[i] = 0;
}
__global__ void count_kernel(const int* __restrict__ eidx) {
    int e = blockIdx.x * blockDim.x + threadIdx.x;
    if (e < N_EDGES) atomicAdd(&g_count[eidx[e]], 1);
}

// phase A: per-block sums of g_count (196 blocks x 256 threads)
__global__ __launch_bounds__(256) void scanA_kernel() {
    __shared__ int ws[8];
    int t = threadIdx.x, i = blockIdx.x * 256 + t;
    int v = (i < N_NODES) ? g_count[i] : 0;
    #pragma unroll
    for (int o = 16; o > 0; o >>= 1) v += __shfl_down_sync(0xffffffffu, v, o);
    if ((t & 31) == 0) ws[t >> 5] = v;
    __syncthreads();
    if (t == 0) {
        int s = 0;
        #pragma unroll
        for (int w = 0; w < 8; w++) s += ws[w];
        g_bsum[blockIdx.x] = s;
    }
}
// phase B: exclusive scan over 196 partials (1 block)
__global__ __launch_bounds__(256) void scanB_kernel() {
    __shared__ int ws[8];
    int t = threadIdx.x, lane = t & 31, w = t >> 5;
    int v = (t < SCAN_BLK) ? g_bsum[t] : 0;
    int x = v;
    #pragma unroll
    for (int o = 1; o < 32; o <<= 1) {
        int y = __shfl_up_sync(0xffffffffu, x, o);
        if (lane >= o) x += y;
    }
    if (lane == 31) ws[w] = x;
    __syncthreads();
    if (t == 0) {
        int run = 0;
        #pragma unroll
        for (int k = 0; k < 8; k++) { int tmp = ws[k]; ws[k] = run; run += tmp; }
    }
    __syncthreads();
    if (t < SCAN_BLK) g_boff[t] = x - v + ws[w];
    if (t == 0) g_off[N_NODES] = N_EDGES;
}
// phase C: local exclusive scan + block offset -> g_off / g_cursor
__global__ __launch_bounds__(256) void scanC_kernel() {
    __shared__ int ws[8];
    int t = threadIdx.x, lane = t & 31, w = t >> 5;
    int i = blockIdx.x * 256 + t;
    int v = (i < N_NODES) ? g_count[i] : 0;
    int x = v;
    #pragma unroll
    for (int o = 1; o < 32; o <<= 1) {
        int y = __shfl_up_sync(0xffffffffu, x, o);
        if (lane >= o) x += y;
    }
    if (lane == 31) ws[w] = x;
    __syncthreads();
    if (t == 0) {
        int run = 0;
        #pragma unroll
        for (int k = 0; k < 8; k++) { int tmp = ws[k]; ws[k] = run; run += tmp; }
    }
    __syncthreads();
    if (i < N_NODES) {
        int excl = x - v + ws[w] + g_boff[blockIdx.x];
        g_off[i] = excl;
        g_cursor[i] = excl;
    }
}
__global__ void scatter_kernel(const int* __restrict__ eidx) {
    int e = blockIdx.x * blockDim.x + threadIdx.x;
    if (e < N_EDGES) {
        int dst = eidx[e];
        int pos = atomicAdd(&g_cursor[dst], 1);
        g_order[pos] = e;
    }
}

// ---------------- kernel 2: fused edge GEMM + conn + score ----------------
// block = 128 edges, 256 threads. thread = 4 edges x 1 head x {Ew(8), Eb(8)}.
__global__ __launch_bounds__(256, 2) void edge_kernel(
    const float* __restrict__ cf, const float* __restrict__ EW,
    const float* __restrict__ Ebias, const int* __restrict__ eidx,
    const float* __restrict__ Aw, float* __restrict__ conn_out)
{
    extern __shared__ float sm[];
    float* cfS = sm;                      // 128*68
    float* wS = cfS + 128 * 68;           // 64*132 : wS[k*132 + n] = EW[n*64+k]
    float* awS = wS + 64 * 132;           // 64
    float* ebS = awS + 64;                // 128
    int* sDst = (int*)(ebS + 128);        // 128
    int* sSrc = sDst + 128;               // 128

    const int tid = threadIdx.x;
    const int e0 = blockIdx.x * 128;

    #pragma unroll
    for (int p = 0; p < 8; p++) {
        int idx = tid + p * 256;          // float4 index over 128x64 cf tile
        int r = idx >> 4, c4 = idx & 15;
        float4 v = ((const float4*)cf)[(e0 + r) * 16 + c4];
        *(float4*)&cfS[r * 68 + c4 * 4] = v;
    }
    #pragma unroll
    for (int p = 0; p < 8; p++) {
        int idx = tid + p * 256;          // float4 index over 128x64 EW
        int n = idx >> 4, f = idx & 15;
        float4 v = ((const float4*)EW)[n * 16 + f];
        wS[(f * 4 + 0) * 132 + n] = v.x;
        wS[(f * 4 + 1) * 132 + n] = v.y;
        wS[(f * 4 + 2) * 132 + n] = v.z;
        wS[(f * 4 + 3) * 132 + n] = v.w;
    }
    if (tid < 64) awS[tid] = Aw[tid];
    if (tid >= 64 && tid < 192) ebS[tid - 64] = Ebias[tid - 64];
    if (tid < 128) {
        sDst[tid] = eidx[e0 + tid];
        sSrc[tid] = eidx[N_EDGES + e0 + tid];
    }
    __syncthreads();

    const int tx = tid & 7;               // head
    const int tg = tid >> 3;              // edge group (4 edges)

    unsigned long long acc[4][8];
    #pragma unroll
    for (int i = 0; i < 4; i++)
        #pragma unroll
        for (int p = 0; p < 8; p++) acc[i][p] = 0ull;

    #pragma unroll 2
    for (int k = 0; k < 64; k++) {
        const float* wr = &wS[k * 132];
        float4 w0 = *(const float4*)&wr[tx * 8];
        float4 w1 = *(const float4*)&wr[tx * 8 + 4];
        float4 w2 = *(const float4*)&wr[64 + tx * 8];
        float4 w3 = *(const float4*)&wr[64 + tx * 8 + 4];
        unsigned long long b[8];
        b[0] = pk2(w0.x, w0.y); b[1] = pk2(w0.z, w0.w);
        b[2] = pk2(w1.x, w1.y); b[3] = pk2(w1.z, w1.w);
        b[4] = pk2(w2.x, w2.y); b[5] = pk2(w2.z, w2.w);
        b[6] = pk2(w3.x, w3.y); b[7] = pk2(w3.z, w3.w);
        #pragma unroll
        for (int i = 0; i < 4; i++) {
            float a = cfS[(tg * 4 + i) * 68 + k];
            unsigned long long a2 = pk2(a, a);
            #pragma unroll
            for (int p = 0; p < 8; p++) fma2(acc[i][p], a2, b[p]);
        }
    }

    // epilogue per edge: conn1 -> signed sqrt -> +Eb -> relu -> write; score -> w
    #pragma unroll
    for (int i = 0; i < 4; i++) {
        int el = tg * 4 + i;
        int e = e0 + el;
        int d = sDst[el], s = sSrc[el];
        float4 q0 = ((const float4*)g_Q)[d * 16 + tx * 2];
        float4 q1 = ((const float4*)g_Q)[d * 16 + tx * 2 + 1];
        float4 k0 = ((const float4*)g_K)[s * 16 + tx * 2];
        float4 k1 = ((const float4*)g_K)[s * 16 + tx * 2 + 1];
        float qk[8] = {q0.x + k0.x, q0.y + k0.y, q0.z + k0.z, q0.w + k0.w,
                       q1.x + k1.x, q1.y + k1.y, q1.z + k1.z, q1.w + k1.w};
        float ew[8], eb[8];
        #pragma unroll
        for (int p = 0; p < 4; p++) {
            float2 u = upk2(acc[i][p]);
            ew[2 * p] = u.x; ew[2 * p + 1] = u.y;
            float2 v = upk2(acc[i][4 + p]);
            eb[2 * p] = v.x; eb[2 * p + 1] = v.y;
        }
        float conn[8];
        #pragma unroll
        for (int j = 0; j < 8; j++) {
            float c1 = qk[j] * (ew[j] + ebS[tx * 8 + j]);
            float c2 = copysignf(sqrtf(fabsf(c1)), c1);
            conn[j] = fmaxf(c2 + (eb[j] + ebS[64 + tx * 8 + j]), 0.f);
        }
        float* co = &conn_out[(long long)e * 64 + tx * 8];
        *(float4*)co = make_float4(conn[0], conn[1], conn[2], conn[3]);
        *(float4*)(co + 4) = make_float4(conn[4], conn[5], conn[6], conn[7]);
        float sc = 0.f;
        #pragma unroll
        for (int j = 0; j < 8; j++) sc = fmaf(conn[j], awS[j * 8 + tx], sc);
        sc = fminf(fmaxf(sc, -CLAMP_V), CLAMP_V);
        g_w[e * 8 + tx] = expf(sc);
    }
}

// ---------------- kernel 3: per-node aggregation (warp per node) ----------------
__global__ __launch_bounds__(256) void node_kernel(
    const float* __restrict__ conn_out, const int* __restrict__ eidx,
    const float* __restrict__ Bw, float* __restrict__ No)
{
    __shared__ float bwS[512];
    int tid = threadIdx.x;
    bwS[tid] = Bw[tid];
    bwS[tid + 256] = Bw[tid + 256];
    __syncthreads();

    const int warp = tid >> 5, lane = tid & 31;
    const int n = blockIdx.x * 8 + warp;
    const int j0 = g_off[n], j1 = g_off[n + 1];
    const int h0 = lane >> 3, h1 = h0 + 4, c = lane & 7, base = lane & 24;
    const int* srcArr = eidx + N_EDGES;

    float s0 = 0.f, s1 = 0.f, agg0 = 0.f, agg1 = 0.f, rv0 = 0.f, rv1 = 0.f;
    int e = (j0 < j1) ? g_order[j0] : 0;
    for (int j = j0; j < j1; j++) {
        int e_next = (j + 1 < j1) ? g_order[j + 1] : 0;  // prefetch: breaks dep chain
        int src = srcArr[e];
        float w0 = g_w[e * 8 + h0];
        float w1 = g_w[e * 8 + h1];
        float c0 = conn_out[(long long)e * 64 + lane];
        float c1 = conn_out[(long long)e * 64 + 32 + lane];
        float v0 = g_V[src * 64 + lane];
        float v1 = g_V[src * 64 + 32 + lane];
        s0 += w0; s1 += w1;
        agg0 = fmaf(w0, v0, agg0); rv0 = fmaf(w0, c0, rv0);
        agg1 = fmaf(w1, v1, agg1); rv1 = fmaf(w1, c1, rv1);
        e = e_next;
    }
    float inv0 = (s0 > 0.f) ? 1.f / s0 : 0.f;
    float inv1 = (s1 > 0.f) ? 1.f / s1 : 0.f;
    float rn0 = rv0 * inv0, rn1 = rv1 * inv1;
    float o0 = 0.f, o1 = 0.f;
    #pragma unroll
    for (int d = 0; d < 8; d++) {
        float r0 = __shfl_sync(0xffffffffu, rn0, base + d);
        float r1 = __shfl_sync(0xffffffffu, rn1, base + d);
        o0 = fmaf(r0, bwS[d * 64 + h0 * 8 + c], o0);
        o1 = fmaf(r1, bwS[d * 64 + h1 * 8 + c], o1);
    }
    No[n * 64 + lane] = fmaf(agg0, inv0, o0);
    No[n * 64 + 32 + lane] = fmaf(agg1, inv1, o1);
}

// ---------------- launch ----------------
extern "C" void kernel_launch(void* const* d_in, const int* in_sizes, int n_in,
                              void* d_out, int out_size)
{
    const float* x       = (const float*)d_in[0];
    const float* cf      = (const float*)d_in[1];
    const int*   eidx    = (const int*)d_in[2];
    const float* qkvW    = (const float*)d_in[3];
    const float* qkvB    = (const float*)d_in[4];
    const float* EW      = (const float*)d_in[5];
    const float* EB      = (const float*)d_in[6];
    const float* Aw      = (const float*)d_in[7];
    const float* Bw      = (const float*)d_in[8];

    float* No = (float*)d_out;
    float* conn_out = No + (size_t)N_NODES * 64;

    const int edge_smem = (128 * 68 + 64 * 132 + 64 + 128) * 4 + 256 * 4;
    cudaFuncSetAttribute(edge_kernel, cudaFuncAttributeMaxDynamicSharedMemorySize, edge_smem);

    // Launch order chosen so the 6th launch (ncu -s 5 -c 1) is edge_kernel.
    // Dependencies: edge needs only qkv; node needs edge + scatter; scanC->scatter.
    zero_kernel<<<(N_NODES + 255) / 256, 256>>>();                         // 1
    qkv_kernel<<<dim3((N_NODES + 63) / 64, 3), 256>>>(x, qkvW, qkvB);      // 2
    count_kernel<<<(N_EDGES + 255) / 256, 256>>>(eidx);                    // 3
    scanA_kernel<<<SCAN_BLK, 256>>>();                                     // 4
    scanB_kernel<<<1, 256>>>();                                            // 5
    edge_kernel<<<N_EDGES / 128, 256, edge_smem>>>(cf, EW, EB, eidx, Aw, conn_out); // 6 <- profiled
    scanC_kernel<<<SCAN_BLK, 256>>>();                                     // 7
    scatter_kernel<<<(N_EDGES + 255) / 256, 256>>>(eidx);                  // 8
    node_kernel<<<N_NODES / 8, 256>>>(conn_out, eidx, Bw, No);             // 9
}